// round 1
// baseline (speedup 1.0000x reference)
#include <cuda_runtime.h>
#include <math.h>

// Problem constants (fixed shapes from reference)
#define N_TOK 16384        // B*T = 16*1024
#define NE    4096         // codebook entries
#define ED    64           // embedding dim
#define BM    128          // tokens per block
#define BK    128          // codes per chunk
#define NCHUNK (NE / BK)   // 32
#define NBLK  (N_TOK / BM) // 128

// Output layout (flattened tuple: loss, z_q_st, idx, perplexity)
#define OUT_ZQ_OFF   1
#define OUT_IDX_OFF  (1 + (size_t)N_TOK * ED)
#define OUT_PERP_OFF (1 + (size_t)N_TOK * ED + N_TOK)

// Scratch (no allocations allowed -> __device__ globals)
__device__ float d_zT [ED * N_TOK];   // transposed z   [d][n]
__device__ float d_cbT[ED * NE];      // transposed cb  [d][k]
__device__ float d_sz [N_TOK];        // ||z_n||^2
__device__ float d_se [NE];           // ||e_k||^2
__device__ int   d_counts[NE];        // code histogram
__device__ float d_losspart[NBLK];    // per-block loss partials

// ---------------------------------------------------------------------------
// prep: tiled transpose (coalesced both ways, conflict-free via +1 pad),
// row squared-norms, zero histogram.
// blocks 0..255: z tiles, 256..319: codebook tiles, 320: zero counts
// ---------------------------------------------------------------------------
__global__ void __launch_bounds__(256) prep_kernel(const float* __restrict__ z,
                                                   const float* __restrict__ cb) {
    int b = blockIdx.x;
    int tid = threadIdx.x;
    if (b >= 320) {
        for (int i = tid; i < NE; i += 256) d_counts[i] = 0;
        return;
    }
    __shared__ float ts[64][65];
    const float* src; float* dst; float* srow; int R; int r0;
    if (b < 256) { src = z;  dst = d_zT;  srow = d_sz; R = N_TOK; r0 = b * 64; }
    else         { src = cb; dst = d_cbT; srow = d_se; R = NE;    r0 = (b - 256) * 64; }

    #pragma unroll
    for (int i = 0; i < 16; i++) {
        int l = tid + i * 256;
        int r = l >> 6, c = l & 63;
        ts[r][c] = src[(size_t)(r0 + r) * ED + c];
    }
    __syncthreads();
    if (tid < 64) {
        float s = 0.f;
        #pragma unroll
        for (int c = 0; c < 64; c++) { float v = ts[tid][c]; s = __fmaf_rn(v, v, s); }
        srow[r0 + tid] = s;
    }
    #pragma unroll
    for (int i = 0; i < 16; i++) {
        int l = tid + i * 256;
        int dd = l >> 6, c = l & 63;
        dst[(size_t)dd * R + r0 + c] = ts[c][dd];
    }
}

// ---------------------------------------------------------------------------
// main: fused distance GEMM + argmin + gather + loss partials
// grid = 128 blocks x 256 threads; block tile = 128 tokens x 4096 codes
// thread micro-tile 8x8 (token rows {4tm..4tm+3, 64+4tm..}, code cols
// {4tk..4tk+3, 64+4tk..}) so LDS.128 reads are conflict-free / broadcast.
// ---------------------------------------------------------------------------
__global__ void __launch_bounds__(256) vq_main(const float* __restrict__ z,
                                               const float* __restrict__ cb,
                                               float* __restrict__ out) {
    extern __shared__ float sm[];
    float* zs  = sm;                    // [64][128]  token tile (transposed)
    float* es  = sm + ED * BM;          // [64][128]  code tile  (transposed)
    float* ses = es + ED * BK;          // [128]      ||e||^2 chunk
    int*   win = (int*)(ses + BK);      // [128]      winning code per token
    float* red = (float*)(win + BM);    // [256]      loss reduction

    int tid = threadIdx.x;
    int tm = tid >> 4, tk = tid & 15;
    int m0 = blockIdx.x * BM;

    // load token tile (coalesced from d_zT, conflict-free STS)
    #pragma unroll
    for (int i = 0; i < 8; i++) {
        int l = tid + i * 256;
        int row = l >> 5, c4 = (l & 31) << 2;
        float4 v = *(const float4*)&d_zT[(size_t)row * N_TOK + m0 + c4];
        *(float4*)&zs[row * BM + c4] = v;
    }

    int mls[8];
    #pragma unroll
    for (int r = 0; r < 8; r++)
        mls[r] = (r < 4) ? (4 * tm + r) : (64 + 4 * tm + (r - 4));

    float szr[8];
    float bd[8]; int bi[8];
    #pragma unroll
    for (int r = 0; r < 8; r++) { bd[r] = 3.402823466e38f; bi[r] = 0; }

    __syncthreads();
    #pragma unroll
    for (int r = 0; r < 8; r++) szr[r] = d_sz[m0 + mls[r]];

    for (int ch = 0; ch < NCHUNK; ch++) {
        int k0 = ch * BK;
        __syncthreads();   // protect es reuse across chunks
        #pragma unroll
        for (int i = 0; i < 8; i++) {
            int l = tid + i * 256;
            int row = l >> 5, c4 = (l & 31) << 2;
            float4 v = *(const float4*)&d_cbT[(size_t)row * NE + k0 + c4];
            *(float4*)&es[row * BK + c4] = v;
        }
        if (tid < BK) ses[tid] = d_se[k0 + tid];
        __syncthreads();

        float acc[8][8];
        #pragma unroll
        for (int r = 0; r < 8; r++)
            #pragma unroll
            for (int c = 0; c < 8; c++) acc[r][c] = 0.f;

        #pragma unroll 4
        for (int d = 0; d < ED; d++) {
            float4 za = *(const float4*)&zs[d * BM + 4 * tm];
            float4 zb = *(const float4*)&zs[d * BM + 64 + 4 * tm];
            float4 ea = *(const float4*)&es[d * BK + 4 * tk];
            float4 eb = *(const float4*)&es[d * BK + 64 + 4 * tk];
            float zr[8] = {za.x, za.y, za.z, za.w, zb.x, zb.y, zb.z, zb.w};
            float ec[8] = {ea.x, ea.y, ea.z, ea.w, eb.x, eb.y, eb.z, eb.w};
            #pragma unroll
            for (int r = 0; r < 8; r++)
                #pragma unroll
                for (int c = 0; c < 8; c++)
                    acc[r][c] = __fmaf_rn(zr[r], ec[c], acc[r][c]);
        }

        // d = round(round(s_z + s_e) - 2*dot), exactly as the reference computes.
        #pragma unroll
        for (int c = 0; c < 8; c++) {
            int kl = (c < 4) ? (4 * tk + c) : (64 + 4 * tk + (c - 4));
            float sek = ses[kl];
            int kg = k0 + kl;
            #pragma unroll
            for (int r = 0; r < 8; r++) {
                float A  = __fadd_rn(szr[r], sek);
                float dv = __fmaf_rn(-2.0f, acc[r][c], A);  // 2*dot exact -> same rounding
                if (dv < bd[r] || (dv == bd[r] && kg < bi[r])) { bd[r] = dv; bi[r] = kg; }
            }
        }
    }

    // argmin reduce across the 16 threads (same tm) sharing each token row.
    // First-index tie-break matches jnp.argmin.
    #pragma unroll
    for (int r = 0; r < 8; r++) {
        float v = bd[r]; int ix = bi[r];
        #pragma unroll
        for (int off = 8; off; off >>= 1) {
            float ov = __shfl_down_sync(0xffffffffu, v, off, 16);
            int   oi = __shfl_down_sync(0xffffffffu, ix, off, 16);
            if (ov < v || (ov == v && oi < ix)) { v = ov; ix = oi; }
        }
        if (tk == 0) win[mls[r]] = ix;
    }
    __syncthreads();

    // idx output + histogram
    if (tid < BM) {
        int ix = win[tid];
        atomicAdd(&d_counts[ix], 1);
        out[OUT_IDX_OFF + m0 + tid] = (float)ix;
    }

    // z_q_st = z + (z_q - z)  (explicit roundings to match reference),
    // loss partial = sum (z_q - z)^2 over this block's 128x64 elements.
    float lacc = 0.f;
    #pragma unroll
    for (int i = 0; i < 32; i++) {
        int l = tid + i * 256;
        int ml = l >> 6, d = l & 63;
        float zq = cb[(size_t)win[ml] * ED + d];
        float zv = z[(size_t)(m0 + ml) * ED + d];
        float t  = __fsub_rn(zq, zv);
        out[OUT_ZQ_OFF + (size_t)(m0 + ml) * ED + d] = __fadd_rn(zv, t);
        lacc = __fmaf_rn(t, t, lacc);
    }
    red[tid] = lacc;
    __syncthreads();
    #pragma unroll
    for (int s = 128; s > 0; s >>= 1) {
        if (tid < s) red[tid] += red[tid + s];
        __syncthreads();
    }
    if (tid == 0) d_losspart[blockIdx.x] = red[0];
}

// ---------------------------------------------------------------------------
// finalize: loss scalar + perplexity scalar
// ---------------------------------------------------------------------------
__global__ void __launch_bounds__(256) vq_finalize(float* __restrict__ out) {
    __shared__ double sh[256];
    int tid = threadIdx.x;

    double s = (tid < NBLK) ? (double)d_losspart[tid] : 0.0;
    sh[tid] = s;
    __syncthreads();
    #pragma unroll
    for (int st = 128; st > 0; st >>= 1) {
        if (tid < st) sh[tid] += sh[tid + st];
        __syncthreads();
    }
    if (tid == 0)
        out[0] = (float)((1.0 + 0.25) * sh[0] / (double)((size_t)N_TOK * ED));
    __syncthreads();

    double h = 0.0;
    for (int i = tid; i < NE; i += 256) {
        float em = (float)d_counts[i] / (float)N_TOK;
        h += (double)(em * logf(em + 1e-10f));
    }
    sh[tid] = h;
    __syncthreads();
    #pragma unroll
    for (int st = 128; st > 0; st >>= 1) {
        if (tid < st) sh[tid] += sh[tid + st];
        __syncthreads();
    }
    if (tid == 0)
        out[OUT_PERP_OFF] = expf(-(float)sh[0]);
}

// ---------------------------------------------------------------------------
extern "C" void kernel_launch(void* const* d_in, const int* in_sizes, int n_in,
                              void* d_out, int out_size) {
    const float* z  = (const float*)d_in[0];   // (16,1024,64) fp32
    const float* cb = (const float*)d_in[1];   // (4096,64)    fp32
    float* out = (float*)d_out;

    // 67.6 KB dynamic smem for the main kernel (over the 48KB default)
    size_t smem = (size_t)(ED * BM + ED * BK + BK) * sizeof(float)
                + BM * sizeof(int) + 256 * sizeof(float);
    cudaFuncSetAttribute(vq_main, cudaFuncAttributeMaxDynamicSharedMemorySize, (int)smem);

    prep_kernel<<<321, 256>>>(z, cb);
    vq_main<<<NBLK, 256, smem>>>(z, cb, out);
    vq_finalize<<<1, 256>>>(out);
}